// round 13
// baseline (speedup 1.0000x reference)
#include <cuda_runtime.h>

typedef unsigned long long u64;

#define H       128
#define SEQ     1024
#define MBLK    4
#define NCTAS   128
#define NTHR    384
#define COUT    10

#define NG      11          // 4-k groups per kt third (44 k, last 4 zero-padded for kt=2)
#define RG      4           // register-resident weight groups (64 regs)
#define SG      (NG - RG)   // 7 groups from smem
#define KPT     44          // k per thread

#define HSTR    136         // h row stride in floats (132 used + pad)
#define HBUF    (MBLK * HSTR)   // 544 floats per buffer

// ---- dynamic smem layout (bytes, 16B aligned) ----
#define WS_OFF    0
#define WS_BYTES  (SG * 4 * NTHR * 16)      // 172032
#define PB_OFF    (WS_OFF + WS_BYTES)
#define PB_BYTES  (3 * 4 * 128 * 16)        // 24576: float4 [kt][m][n]
#define XS_OFF    (PB_OFF + PB_BYTES)
#define XS_BYTES  (MBLK * SEQ * 4)          // 16384
#define WPS_OFF   (XS_OFF + XS_BYTES)
#define WPS_BYTES (H * COUT * 4)            // 5120
#define HB_OFF    (WPS_OFF + WPS_BYTES)
#define HB_BYTES  (2 * HBUF * 4)            // 4352
#define SMEM_TOTAL (HB_OFF + HB_BYTES + 64) // 222528 <= 227 KB

__device__ __forceinline__ u64 pk2(float lo, float hi) {
    u64 r;
    asm("mov.b64 %0, {%1, %2};" : "=l"(r) : "f"(lo), "f"(hi));
    return r;
}
__device__ __forceinline__ void upk2(u64 v, float& lo, float& hi) {
    asm("mov.b64 {%0, %1}, %2;" : "=f"(lo), "=f"(hi) : "l"(v));
}
__device__ __forceinline__ u64 ffma2(u64 a, u64 b, u64 c) {
    u64 d;
    asm("fma.rn.f32x2 %0, %1, %2, %3;" : "=l"(d) : "l"(a), "l"(b), "l"(c));
    return d;
}

// Fused LSTM cell (validated rel_err ~2.8e-7 in R8-R11). Overflow-safe.
__device__ __forceinline__ float lstm_cell(float zg, float zi, float zf, float zo, float& c) {
    float eg = __expf(-2.0f * fabsf(zg));
    float ei = __expf(-zi);
    float ef = __expf(-zf);
    float eo = __expf(-zo);
    float gi = __fdividef(copysignf(1.0f - eg, zg), (1.0f + eg) * (1.0f + ei));
    float cf = __fdividef(c, 1.0f + ef);
    float cn = gi + cf;
    float ec = __expf(-2.0f * fabsf(cn));
    float h  = __fdividef(copysignf(1.0f - ec, cn), (1.0f + ec) * (1.0f + eo));
    c = cn;
    return h;
}

__global__ void __launch_bounds__(NTHR, 1)
lstm_persistent_kernel(const float* __restrict__ x,
                       const float* __restrict__ Wgx, const float* __restrict__ Wgh, const float* __restrict__ bg,
                       const float* __restrict__ Wix, const float* __restrict__ Wih, const float* __restrict__ bi,
                       const float* __restrict__ Wfx, const float* __restrict__ Wfh, const float* __restrict__ bf,
                       const float* __restrict__ Wox, const float* __restrict__ Woh, const float* __restrict__ bo,
                       const float* __restrict__ Wph, const float* __restrict__ bp,
                       float* __restrict__ out)
{
    extern __shared__ char smem[];
    ulonglong2* ws = (ulonglong2*)(smem + WS_OFF);
    float4*    pb4 = (float4*)(smem + PB_OFF);
    float*     xsm = (float*)(smem + XS_OFF);
    float*     wps = (float*)(smem + WPS_OFF);
    float*      hb = (float*)(smem + HB_OFF);

    const int tid = threadIdx.x;
    const int kt  = tid >> 7;          // k third: [kt*44, kt*44+44)
    const int n   = tid & 127;         // gate column
    const int m0  = blockIdx.x * MBLK;
    const int kb  = kt * KPT;

    // safe weight fetch (zero-pad k >= 128)
#define WQ(W, k)  ((k) < H ? (W)[(k) * H + n] : 0.0f)

    // ---- smem weights: groups RG..NG-1 of slice (kt, n) ----
    // ws[(sg*4+q)*NTHR + tid]: q0={g,i}(k0,k1) q1={f,o}(k0,k1) q2={g,i}(k2,k3) q3={f,o}(k2,k3)
#pragma unroll
    for (int sg = 0; sg < SG; sg++) {
        int k0 = kb + (RG + sg) * 4;
        ulonglong2 v;
        v.x = pk2(WQ(Wgh,k0+0), WQ(Wgh,k0+1));
        v.y = pk2(WQ(Wih,k0+0), WQ(Wih,k0+1));
        ws[(sg*4+0)*NTHR + tid] = v;
        v.x = pk2(WQ(Wfh,k0+0), WQ(Wfh,k0+1));
        v.y = pk2(WQ(Woh,k0+0), WQ(Woh,k0+1));
        ws[(sg*4+1)*NTHR + tid] = v;
        v.x = pk2(WQ(Wgh,k0+2), WQ(Wgh,k0+3));
        v.y = pk2(WQ(Wih,k0+2), WQ(Wih,k0+3));
        ws[(sg*4+2)*NTHR + tid] = v;
        v.x = pk2(WQ(Wfh,k0+2), WQ(Wfh,k0+3));
        v.y = pk2(WQ(Woh,k0+2), WQ(Woh,k0+3));
        ws[(sg*4+3)*NTHR + tid] = v;
    }

    // ---- register weights: groups 0..RG-1 (8 u64 each = 64 regs) ----
    u64 wreg[RG][8];
#pragma unroll
    for (int g = 0; g < RG; g++) {
        int k0 = kb + g * 4;
        wreg[g][0] = pk2(WQ(Wgh,k0+0), WQ(Wgh,k0+1));
        wreg[g][1] = pk2(WQ(Wih,k0+0), WQ(Wih,k0+1));
        wreg[g][2] = pk2(WQ(Wfh,k0+0), WQ(Wfh,k0+1));
        wreg[g][3] = pk2(WQ(Woh,k0+0), WQ(Woh,k0+1));
        wreg[g][4] = pk2(WQ(Wgh,k0+2), WQ(Wgh,k0+3));
        wreg[g][5] = pk2(WQ(Wih,k0+2), WQ(Wih,k0+3));
        wreg[g][6] = pk2(WQ(Wfh,k0+2), WQ(Wfh,k0+3));
        wreg[g][7] = pk2(WQ(Woh,k0+2), WQ(Woh,k0+3));
    }
#undef WQ

    // ---- gate-phase cell ownership: m = kt; kt==0 also owns m = 3 ----
    const int mA = kt;
    const bool two = (kt == 0);
    const float wxg = Wgx[n], wxi = Wix[n], wxf = Wfx[n], wxo = Wox[n];
    const float bGa = bg[(m0+mA)*H+n], bIa = bi[(m0+mA)*H+n];
    const float bFa = bf[(m0+mA)*H+n], bOa = bo[(m0+mA)*H+n];
    const float bGb = bg[(m0+3)*H+n],  bIb = bi[(m0+3)*H+n];
    const float bFb = bf[(m0+3)*H+n],  bOb = bo[(m0+3)*H+n];

    // foreign kt slots for the exchange
    const int kt1 = (kt + 1 == 3) ? 0 : kt + 1;
    const int kt2 = (kt + 2 >= 3) ? kt - 1 + ((kt==0)?0:0) : kt + 2;
    const int ktx = (kt1 == 0 && kt2 == 0) ? 0 : 0; (void)ktx; // (silence)
    // recompute cleanly:
    const int f1 = (kt == 2) ? 0 : kt + 1;
    const int f2 = (kt == 0) ? 2 : kt - 1;

    // ---- preload x, Wph, zero both h buffers ----
    for (int i = tid; i < MBLK * SEQ; i += NTHR) {
        int mm = i >> 10, tt = i & (SEQ - 1);
        xsm[i] = x[(m0+mm)*SEQ + tt];
    }
    for (int i = tid; i < H * COUT; i += NTHR) wps[i] = Wph[i];
    for (int i = tid; i < 2 * HBUF; i += NTHR) hb[i] = 0.0f;
    float cA = 0.0f, cB = 0.0f;
    __syncthreads();

    const float* xA = xsm + mA * SEQ;
    const float* xB = xsm + 3 * SEQ;
    const int hstA = mA * HSTR + n;
    const int hstB = 3 * HSTR + n;

    // ---- time loop: 2 barriers per step ----
    for (int t = 0; t < SEQ; t++) {
        const float* hr = hb + ((t & 1) ? HBUF : 0);
        float*       hw = hb + ((t & 1) ? 0 : HBUF);

        u64 acc[4][4];   // [gate][m], k-pair packed
#pragma unroll
        for (int gg = 0; gg < 4; gg++)
#pragma unroll
            for (int m = 0; m < 4; m++) acc[gg][m] = 0ull;

#pragma unroll
        for (int g = 0; g < NG; g++) {
            u64 wg0, wi0, wf0, wo0, wg1, wi1, wf1, wo1;
            if (g < RG) {
                wg0 = wreg[g][0]; wi0 = wreg[g][1]; wf0 = wreg[g][2]; wo0 = wreg[g][3];
                wg1 = wreg[g][4]; wi1 = wreg[g][5]; wf1 = wreg[g][6]; wo1 = wreg[g][7];
            } else {
                int sg = g - RG;
                ulonglong2 q0 = ws[(sg*4+0)*NTHR + tid];
                ulonglong2 q1 = ws[(sg*4+1)*NTHR + tid];
                ulonglong2 q2 = ws[(sg*4+2)*NTHR + tid];
                ulonglong2 q3 = ws[(sg*4+3)*NTHR + tid];
                wg0 = q0.x; wi0 = q0.y; wf0 = q1.x; wo0 = q1.y;
                wg1 = q2.x; wi1 = q2.y; wf1 = q3.x; wo1 = q3.y;
            }
            const int hbase = kb + (g << 2);
#pragma unroll
            for (int m = 0; m < 4; m++) {
                // warp-uniform broadcast 16B load: {h[k0..k3]} of row m -> 1 wf
                ulonglong2 hu = *(const ulonglong2*)(hr + m * HSTR + hbase);
                acc[0][m] = ffma2(hu.x, wg0, acc[0][m]);
                acc[1][m] = ffma2(hu.x, wi0, acc[1][m]);
                acc[2][m] = ffma2(hu.x, wf0, acc[2][m]);
                acc[3][m] = ffma2(hu.x, wo0, acc[3][m]);
                acc[0][m] = ffma2(hu.y, wg1, acc[0][m]);
                acc[1][m] = ffma2(hu.y, wi1, acc[1][m]);
                acc[2][m] = ffma2(hu.y, wf1, acc[2][m]);
                acc[3][m] = ffma2(hu.y, wo1, acc[3][m]);
            }
        }

        // collapse k-pairs -> p[gate][m]
        float p[4][4];
#pragma unroll
        for (int gg = 0; gg < 4; gg++)
#pragma unroll
            for (int m = 0; m < 4; m++) {
                float lo, hi;
                upk2(acc[gg][m], lo, hi);
                p[gg][m] = lo + hi;
            }

        // publish partials: pb4[kt][m][n] (contiguous float4 per warp -> 4 wf each)
#pragma unroll
        for (int m = 0; m < 4; m++)
            pb4[(kt * 4 + m) * 128 + n] = make_float4(p[0][m], p[1][m], p[2][m], p[3][m]);
        __syncthreads();

        // gates for owned cell(s): sum own partial + two foreign slots
        {
            float4 a1 = pb4[(f1 * 4 + mA) * 128 + n];
            float4 a2 = pb4[(f2 * 4 + mA) * 128 + n];
            float xv = xA[t];
            float zg = p[0][mA] + a1.x + a2.x + fmaf(xv, wxg, bGa);
            float zi = p[1][mA] + a1.y + a2.y + fmaf(xv, wxi, bIa);
            float zf = p[2][mA] + a1.z + a2.z + fmaf(xv, wxf, bFa);
            float zo = p[3][mA] + a1.w + a2.w + fmaf(xv, wxo, bOa);
            hw[hstA] = lstm_cell(zg, zi, zf, zo, cA);
        }
        if (two) {
            float4 a1 = pb4[(1 * 4 + 3) * 128 + n];
            float4 a2 = pb4[(2 * 4 + 3) * 128 + n];
            float xv = xB[t];
            float zg = p[0][3] + a1.x + a2.x + fmaf(xv, wxg, bGb);
            float zi = p[1][3] + a1.y + a2.y + fmaf(xv, wxi, bIb);
            float zf = p[2][3] + a1.z + a2.z + fmaf(xv, wxf, bFb);
            float zo = p[3][3] + a1.w + a2.w + fmaf(xv, wxo, bOb);
            hw[hstB] = lstm_cell(zg, zi, zf, zo, cB);
        }
        __syncthreads();   // h + pbuf reuse safe for next step
    }

    // ---- final projection: h ends in buffer 0 after SEQ (even) steps ----
    const float* hf = hb;
    if (tid < MBLK * COUT) {
        int m = tid / COUT, cc = tid - m * COUT;
        float ssum = bp[(m0+m)*COUT + cc];
#pragma unroll 16
        for (int k = 0; k < H; k++)
            ssum = fmaf(hf[m * HSTR + k], wps[k*COUT + cc], ssum);
        out[(m0+m)*COUT + cc] = ssum;
    }
}

extern "C" void kernel_launch(void* const* d_in, const int* in_sizes, int n_in,
                              void* d_out, int out_size) {
    const float* x   = (const float*)d_in[0];
    const float* Wgx = (const float*)d_in[1];
    const float* Wgh = (const float*)d_in[2];
    const float* bg  = (const float*)d_in[3];
    const float* Wix = (const float*)d_in[4];
    const float* Wih = (const float*)d_in[5];
    const float* bi  = (const float*)d_in[6];
    const float* Wfx = (const float*)d_in[7];
    const float* Wfh = (const float*)d_in[8];
    const float* bf  = (const float*)d_in[9];
    const float* Wox = (const float*)d_in[10];
    const float* Woh = (const float*)d_in[11];
    const float* bo  = (const float*)d_in[12];
    const float* Wph = (const float*)d_in[13];
    const float* bp  = (const float*)d_in[14];
    float* out = (float*)d_out;

    cudaFuncSetAttribute(lstm_persistent_kernel,
                         cudaFuncAttributeMaxDynamicSharedMemorySize, SMEM_TOTAL);

    lstm_persistent_kernel<<<NCTAS, NTHR, SMEM_TOTAL>>>(
        x, Wgx, Wgh, bg, Wix, Wih, bi, Wfx, Wfh, bf, Wox, Woh, bo, Wph, bp, out);
}

// round 14
// speedup vs baseline: 1.0405x; 1.0405x over previous
#include <cuda_runtime.h>

typedef unsigned long long u64;

#define H       128
#define SEQ     1024
#define MBLK    4
#define NCTAS   128
#define NTHR    512
#define COUT    10

#define NG      16          // 4-k groups per kh half (64 k per thread)
#define RG      9           // register-resident weight groups (9*4 u64 = 72 regs)
#define SG      (NG - RG)   // 7 groups from smem

#define HSTRIDE 136         // h row stride floats; hoff skew -> kh spans bank-disjoint
#define HBUF    (MBLK * HSTRIDE)    // 544

// h skew: float offset of h[k] within a row = k + (k>>6)*4
__device__ __forceinline__ int hoff(int k) { return k + ((k >> 6) << 2); }

// ---- dynamic smem layout (bytes, 16B aligned) ----
#define WS_OFF    0
#define WS_BYTES  (SG * 2 * NTHR * 16)      // 114688: ulonglong2 [(sg*2+q)][tid]
#define XS_OFF    (WS_OFF + WS_BYTES)
#define XS_BYTES  (MBLK * SEQ * 4)          // 16384
#define WPS_OFF   (XS_OFF + XS_BYTES)
#define WPS_BYTES (H * COUT * 4)            // 5120
#define PB_OFF    (WPS_OFF + WPS_BYTES)
#define PB_BYTES  (MBLK * 132 * 8)          // 4224: float2 [m][132]
#define HB_OFF    (PB_OFF + PB_BYTES)
#define HB_BYTES  (2 * HBUF * 4)            // 4352
#define SMEM_TOTAL (HB_OFF + HB_BYTES + 64) // ~142 KB (leaves ~86 KB L1D)

__device__ __forceinline__ u64 pk2(float lo, float hi) {
    u64 r;
    asm("mov.b64 %0, {%1, %2};" : "=l"(r) : "f"(lo), "f"(hi));
    return r;
}
__device__ __forceinline__ void upk2(u64 v, float& lo, float& hi) {
    asm("mov.b64 {%0, %1}, %2;" : "=f"(lo), "=f"(hi) : "l"(v));
}
__device__ __forceinline__ u64 ffma2(u64 a, u64 b, u64 c) {
    u64 d;
    asm("fma.rn.f32x2 %0, %1, %2, %3;" : "=l"(d) : "l"(a), "l"(b), "l"(c));
    return d;
}

// Fused LSTM cell (validated rel_err ~2.8e-7 across R8-R13). Overflow-safe.
__device__ __forceinline__ float lstm_cell(float zg, float zi, float zf, float zo, float& c) {
    float eg = __expf(-2.0f * fabsf(zg));
    float ei = __expf(-zi);
    float ef = __expf(-zf);
    float eo = __expf(-zo);
    float gi = __fdividef(copysignf(1.0f - eg, zg), (1.0f + eg) * (1.0f + ei));
    float cf = __fdividef(c, 1.0f + ef);
    float cn = gi + cf;
    float ec = __expf(-2.0f * fabsf(cn));
    float h  = __fdividef(copysignf(1.0f - ec, cn), (1.0f + ec) * (1.0f + eo));
    c = cn;
    return h;
}

__global__ void __launch_bounds__(NTHR, 1)
lstm_persistent_kernel(const float* __restrict__ x,
                       const float* __restrict__ Wgx, const float* __restrict__ Wgh, const float* __restrict__ bg,
                       const float* __restrict__ Wix, const float* __restrict__ Wih, const float* __restrict__ bi,
                       const float* __restrict__ Wfx, const float* __restrict__ Wfh, const float* __restrict__ bf,
                       const float* __restrict__ Wox, const float* __restrict__ Woh, const float* __restrict__ bo,
                       const float* __restrict__ Wph, const float* __restrict__ bp,
                       float* __restrict__ out)
{
    extern __shared__ char smem[];
    ulonglong2* ws = (ulonglong2*)(smem + WS_OFF);
    float*     xsm = (float*)(smem + XS_OFF);
    float*     wps = (float*)(smem + WPS_OFF);
    float2*    pb2 = (float2*)(smem + PB_OFF);
    float*      hb = (float*)(smem + HB_OFF);

    const int tid = threadIdx.x;
    const int kh  = tid & 1;            // k-half [kh*64, kh*64+64); partner = adjacent lane
    const int n   = (tid >> 1) & 127;   // gate column
    const int gh  = tid >> 8;           // gate half: 0 -> (g,i), 1 -> (f,o)
    const int m0  = blockIdx.x * MBLK;

    const int ob = 2 * gh;              // own row base (rows ob, ob+1)
    const int pbm = 2 - 2 * gh;         // partner row base
    const int mo = ob + kh;             // owned cell row
    const int mp = pbm + kh;            // partner cell row (same kh)

    const float* WA = gh ? Wfh : Wgh;
    const float* WB = gh ? Woh : Wih;

    // ---- smem weights: groups RG..NG-1 of slice (gh, kh, n) ----
    // ws[(sg*2+q)*NTHR + tid]: q0 = {A(k0,k1), B(k0,k1)}, q1 = {A(k2,k3), B(k2,k3)}
#pragma unroll
    for (int sg = 0; sg < SG; sg++) {
        int k0 = kh * 64 + (RG + sg) * 4;
        ulonglong2 v;
        v.x = pk2(WA[(k0+0)*H+n], WA[(k0+1)*H+n]);
        v.y = pk2(WB[(k0+0)*H+n], WB[(k0+1)*H+n]);
        ws[(sg*2+0)*NTHR + tid] = v;
        v.x = pk2(WA[(k0+2)*H+n], WA[(k0+3)*H+n]);
        v.y = pk2(WB[(k0+2)*H+n], WB[(k0+3)*H+n]);
        ws[(sg*2+1)*NTHR + tid] = v;
    }

    // ---- register weights: groups 0..RG-1 (4 u64 each = 72 regs total) ----
    u64 wreg[RG][4];
#pragma unroll
    for (int g = 0; g < RG; g++) {
        int k0 = kh * 64 + g * 4;
        wreg[g][0] = pk2(WA[(k0+0)*H+n], WA[(k0+1)*H+n]);
        wreg[g][1] = pk2(WB[(k0+0)*H+n], WB[(k0+1)*H+n]);
        wreg[g][2] = pk2(WA[(k0+2)*H+n], WA[(k0+3)*H+n]);
        wreg[g][3] = pk2(WB[(k0+2)*H+n], WB[(k0+3)*H+n]);
    }

    // ---- gate-phase params for the one owned cell (row mo, col n) ----
    const float wxg = Wgx[n], wxi = Wix[n], wxf = Wfx[n], wxo = Wox[n];
    const float bG = bg[(m0+mo)*H+n], bI = bi[(m0+mo)*H+n];
    const float bF = bf[(m0+mo)*H+n], bO = bo[(m0+mo)*H+n];

    // ---- preload x, Wph; zero h buffers ----
    for (int i = tid; i < MBLK * SEQ; i += NTHR) {
        int mm = i >> 10, tt = i & (SEQ - 1);
        xsm[i] = x[(m0+mm)*SEQ + tt];
    }
    for (int i = tid; i < H * COUT; i += NTHR) wps[i] = Wph[i];
    for (int i = tid; i < 2 * HBUF; i += NTHR) hb[i] = 0.0f;
    float c = 0.0f;
    __syncthreads();

    const int hload0 = kh * 68;                   // skewed base of this kh half
    const int hst = mo * HSTRIDE + hoff(n);       // own h store offset
    const float* xrow = xsm + mo * SEQ;

    // ---- time loop: 2 barriers per step ----
    for (int t = 0; t < SEQ; t++) {
        const float* hr = hb + ((t & 1) ? HBUF : 0);
        float*       hw = hb + ((t & 1) ? 0 : HBUF);

        u64 accA[4], accB[4];
#pragma unroll
        for (int m = 0; m < 4; m++) { accA[m] = 0ull; accB[m] = 0ull; }

#pragma unroll
        for (int g = 0; g < NG; g++) {
            u64 wA0, wB0, wA1, wB1;
            if (g < RG) {
                wA0 = wreg[g][0]; wB0 = wreg[g][1];
                wA1 = wreg[g][2]; wB1 = wreg[g][3];
            } else {
                int sg = g - RG;
                ulonglong2 q0 = ws[(sg*2+0)*NTHR + tid];
                ulonglong2 q1 = ws[(sg*2+1)*NTHR + tid];
                wA0 = q0.x; wB0 = q0.y; wA1 = q1.x; wB1 = q1.y;
            }
            const int hbase = hload0 + (g << 2);
#pragma unroll
            for (int m = 0; m < 4; m++) {
                // 16B load {h[k0..k3]} row m: 2 kh spans bank-disjoint -> 1 wf
                ulonglong2 hu = *(const ulonglong2*)(hr + m * HSTRIDE + hbase);
                accA[m] = ffma2(hu.x, wA0, accA[m]);
                accB[m] = ffma2(hu.x, wB0, accB[m]);
                accA[m] = ffma2(hu.y, wA1, accA[m]);
                accB[m] = ffma2(hu.y, wB1, accB[m]);
            }
        }

        // collapse k-pairs -> per-row partials
        float pA[4], pB[4];
#pragma unroll
        for (int m = 0; m < 4; m++) {
            float lo, hi;
            upk2(accA[m], lo, hi); pA[m] = lo + hi;
            upk2(accB[m], lo, hi); pB[m] = lo + hi;
        }

        // extract own-base and partner-base rows (gh-uniform selects)
        float Ao0 = gh ? pA[2] : pA[0], Ao1 = gh ? pA[3] : pA[1];
        float Bo0 = gh ? pB[2] : pB[0], Bo1 = gh ? pB[3] : pB[1];
        float Ap0 = gh ? pA[0] : pA[2], Ap1 = gh ? pA[1] : pA[3];
        float Bp0 = gh ? pB[0] : pB[2], Bp1 = gh ? pB[1] : pB[3];

        // kh butterfly (lane xor 1): send the row the PARTNER owns, keep mine
        const bool k1 = (kh != 0);
        float fAo = (k1 ? Ao1 : Ao0) + __shfl_xor_sync(0xFFFFFFFFu, k1 ? Ao0 : Ao1, 1);
        float fBo = (k1 ? Bo1 : Bo0) + __shfl_xor_sync(0xFFFFFFFFu, k1 ? Bo0 : Bo1, 1);
        float fAp = (k1 ? Ap1 : Ap0) + __shfl_xor_sync(0xFFFFFFFFu, k1 ? Ap0 : Ap1, 1);
        float fBp = (k1 ? Bp1 : Bp0) + __shfl_xor_sync(0xFFFFFFFFu, k1 ? Bp0 : Bp1, 1);

        // gh exchange: give my 2 gates for the partner's cell, take theirs for mine
        pb2[mp * 132 + n] = make_float2(fAp, fBp);
        __syncthreads();
        float2 r2 = pb2[mo * 132 + n];

        // gates for the one owned cell
        {
            float xv = xrow[t];
            float zg = (gh ? r2.x : fAo) + fmaf(xv, wxg, bG);
            float zi = (gh ? r2.y : fBo) + fmaf(xv, wxi, bI);
            float zf = (gh ? fAo : r2.x) + fmaf(xv, wxf, bF);
            float zo = (gh ? fBo : r2.y) + fmaf(xv, wxo, bO);
            hw[hst] = lstm_cell(zg, zi, zf, zo, c);
        }
        __syncthreads();   // new h + pbuf reuse safe
    }

    // ---- final projection: h ends in buffer 0 after SEQ (even) steps ----
    const float* hf = hb;
    if (tid < MBLK * COUT) {
        int m = tid / COUT, cc = tid - m * COUT;
        float ssum = bp[(m0+m)*COUT + cc];
#pragma unroll 16
        for (int k = 0; k < H; k++)
            ssum = fmaf(hf[m * HSTRIDE + hoff(k)], wps[k*COUT + cc], ssum);
        out[(m0+m)*COUT + cc] = ssum;
    }
}

extern "C" void kernel_launch(void* const* d_in, const int* in_sizes, int n_in,
                              void* d_out, int out_size) {
    const float* x   = (const float*)d_in[0];
    const float* Wgx = (const float*)d_in[1];
    const float* Wgh = (const float*)d_in[2];
    const float* bg  = (const float*)d_in[3];
    const float* Wix = (const float*)d_in[4];
    const float* Wih = (const float*)d_in[5];
    const float* bi  = (const float*)d_in[6];
    const float* Wfx = (const float*)d_in[7];
    const float* Wfh = (const float*)d_in[8];
    const float* bf  = (const float*)d_in[9];
    const float* Wox = (const float*)d_in[10];
    const float* Woh = (const float*)d_in[11];
    const float* bo  = (const float*)d_in[12];
    const float* Wph = (const float*)d_in[13];
    const float* bp  = (const float*)d_in[14];
    float* out = (float*)d_out;

    cudaFuncSetAttribute(lstm_persistent_kernel,
                         cudaFuncAttributeMaxDynamicSharedMemorySize, SMEM_TOTAL);

    lstm_persistent_kernel<<<NCTAS, NTHR, SMEM_TOTAL>>>(
        x, Wgx, Wgh, bg, Wix, Wih, bi, Wfx, Wfh, bf, Wox, Woh, bo, Wph, bp, out);
}